// round 10
// baseline (speedup 1.0000x reference)
#include <cuda_runtime.h>
#include <cuda_fp16.h>
#include <math.h>
#include <stdint.h>

#define D_MODEL 1024
#define SEQ     2048
#define NHEADS  16
#define HDIM    64
#define BATCH   4
#define MTOT    (BATCH*SEQ)
#define NQKV    3072

// Scratch (allocation-free rule: __device__ globals)
__device__ __half g_X16[(size_t)MTOT * D_MODEL];
__device__ __half g_Wqkv[(size_t)D_MODEL * NQKV];     // [k][3*1024] interleaved
__device__ __half g_Wo16[(size_t)D_MODEL * D_MODEL];
__device__ float  g_Bqkv[NQKV];
__device__ __half g_QKV[(size_t)MTOT * NQKV];         // fused Q|K|V rows
__device__ __half g_A16[(size_t)MTOT * D_MODEL];
__device__ float2 g_RT[(size_t)SEQ * 512];            // RoPE cos/sin table

// ---------------------------------------------------------------------------
// helpers
// ---------------------------------------------------------------------------
__device__ __forceinline__ void mma_f16(float* d, const unsigned* a, const unsigned* b) {
    asm volatile(
        "mma.sync.aligned.m16n8k16.row.col.f32.f16.f16.f32 "
        "{%0,%1,%2,%3}, {%4,%5,%6,%7}, {%8,%9}, {%0,%1,%2,%3};\n"
        : "+f"(d[0]), "+f"(d[1]), "+f"(d[2]), "+f"(d[3])
        : "r"(a[0]), "r"(a[1]), "r"(a[2]), "r"(a[3]), "r"(b[0]), "r"(b[1]));
}
__device__ __forceinline__ unsigned pack_h2(float lo, float hi) {
    unsigned r; asm("cvt.rn.f16x2.f32 %0, %1, %2;" : "=r"(r) : "f"(hi), "f"(lo));
    return r;
}
__device__ __forceinline__ void ldsm4(unsigned* r, uint32_t addr) {
    asm volatile("ldmatrix.sync.aligned.m8n8.x4.shared.b16 {%0,%1,%2,%3}, [%4];"
                 : "=r"(r[0]), "=r"(r[1]), "=r"(r[2]), "=r"(r[3]) : "r"(addr));
}
__device__ __forceinline__ void ldsm4t(unsigned* r, uint32_t addr) {
    asm volatile("ldmatrix.sync.aligned.m8n8.x4.trans.shared.b16 {%0,%1,%2,%3}, [%4];"
                 : "=r"(r[0]), "=r"(r[1]), "=r"(r[2]), "=r"(r[3]) : "r"(addr));
}
__device__ __forceinline__ uint32_t smem_u32(const void* p) {
    uint32_t a;
    asm("{ .reg .u64 t; cvta.to.shared.u64 t, %1; cvt.u32.u64 %0, t; }" : "=r"(a) : "l"(p));
    return a;
}
__device__ __forceinline__ void cpa16(uint32_t dst, const void* src) {
    asm volatile("cp.async.cg.shared.global [%0], [%1], 16;" :: "r"(dst), "l"(src));
}
#define CPA_COMMIT() asm volatile("cp.async.commit_group;" ::: "memory")
#define CPA_WAIT(n)  asm volatile("cp.async.wait_group %0;" :: "n"(n) : "memory")

// exp2 on the FMA pipe (no MUFU). Valid for x <= ~0; clamps at -125.
__device__ __forceinline__ float fexp2(float x) {
    x = fmaxf(x, -125.f);
    float t = x + 12582912.f;
    int  ix = __float_as_int(t) - 0x4B400000;
    float f = x - (t - 12582912.f);
    float p = 1.3333558146e-3f;
    p = fmaf(p, f, 9.6181291076e-3f);
    p = fmaf(p, f, 5.5504108665e-2f);
    p = fmaf(p, f, 2.4022650696e-1f);
    p = fmaf(p, f, 6.9314718056e-1f);
    p = fmaf(p, f, 1.0f);
    return p * __int_as_float((ix + 127) << 23);
}

// ===========================================================================
// converters
// ===========================================================================
__global__ __launch_bounds__(256) void cvtX(const float4* __restrict__ X4,
                                            __half* __restrict__ O) {
    const size_t i = (size_t)blockIdx.x * 256 + threadIdx.x;
    float4 a = X4[2*i], b = X4[2*i + 1];
    uint4 o;
    o.x = pack_h2(a.x, a.y); o.y = pack_h2(a.z, a.w);
    o.z = pack_h2(b.x, b.y); o.w = pack_h2(b.z, b.w);
    *(uint4*)(O + 8*i) = o;
}
// All four weight matrices in one launch. Wq/Wk/Wv -> interleaved [k][3072];
// Wo -> flat fp16.
#define WCHUNK ((size_t)D_MODEL * D_MODEL / 8)
__global__ __launch_bounds__(256) void cvtW4(
    const float4* __restrict__ Wq, const float4* __restrict__ Wk,
    const float4* __restrict__ Wv, const float4* __restrict__ Wo) {
    const size_t gi = (size_t)blockIdx.x * 256 + threadIdx.x;
    const int which = (int)(gi / WCHUNK);
    const size_t j = gi % WCHUNK;
    const float4* src = (which == 0) ? Wq : (which == 1) ? Wk : (which == 2) ? Wv : Wo;
    float4 a = src[2*j], b = src[2*j + 1];
    uint4 o;
    o.x = pack_h2(a.x, a.y); o.y = pack_h2(a.z, a.w);
    o.z = pack_h2(b.x, b.y); o.w = pack_h2(b.z, b.w);
    if (which < 3) {
        const size_t k = (8*j) >> 10, n = (8*j) & 1023;
        *(uint4*)(g_Wqkv + k * NQKV + which * 1024 + n) = o;
    } else {
        *(uint4*)(g_Wo16 + 8*j) = o;
    }
}
__global__ __launch_bounds__(256) void fuse_bias(const float* __restrict__ bq,
                                                 const float* __restrict__ bk,
                                                 const float* __restrict__ bv) {
    const int i = blockIdx.x * 256 + threadIdx.x;
    g_Bqkv[i] = (i < 1024) ? bq[i] : (i < 2048 ? bk[i - 1024] : bv[i - 2048]);
}
__global__ __launch_bounds__(256) void rope_table() {
    const int i = blockIdx.x * 256 + threadIdx.x;
    const int pos = i >> 9, p = i & 511;
    const float NEG_L2B = -0.02595256324130752f;
    const float fr = exp2f((float)p * NEG_L2B);
    float s, c; sincosf((float)pos * fr, &s, &c);
    g_RT[i] = make_float2(c, s);
}

// ===========================================================================
// fp16 GEMM (m16n8k16): C = A16 @ W16 + bias, RoPE iff col < ropeLimit.
// CTA 128x128, BK=64, 3-stage cp.async, ldmatrix fragments.
// ===========================================================================
#define G_AST 144                    // 64 halves + 8 pad (bytes)
#define G_BST 272                    // 128 halves + 8 pad (bytes)
#define G_ASZ (128*G_AST)            // 18432
#define G_BSZ (64*G_BST)             // 17408
#define G_STG (G_ASZ + G_BSZ)        // 35840
#define GEMM_SMEM (3*G_STG)          // 107520 B
#define NCH (D_MODEL/64)             // 16

__global__ __launch_bounds__(256, 2) void gemm_f16(
    const __half* __restrict__ A16, const __half* __restrict__ W16,
    const float* __restrict__ bias, float* __restrict__ Cf,
    __half* __restrict__ Ch, int outHalf, int ropeLimit, int ldb, int ldc)
{
    extern __shared__ char smc[];
    const uint32_t s0 = smem_u32(smc);

    const int t = threadIdx.x, lane = t & 31, wid = t >> 5;
    const int lg = lane >> 2, lc = lane & 3;
    const int wm = (wid >> 2) * 64, wn = (wid & 3) * 32;
    const int m0 = blockIdx.y * 128, n0 = blockIdx.x * 128;

    // A loader: 2 threads/row, 64B each (4 x 16B)
    const __half* Asrc = A16 + (size_t)(m0 + (t >> 1)) * D_MODEL + (t & 1) * 32;
    const uint32_t a_dst = s0 + (uint32_t)((t >> 1) * G_AST + (t & 1) * 64);
    // B loader: 4 threads/row, 64B each
    const __half* Bsrc = W16 + (size_t)(t >> 2) * ldb + n0 + (t & 3) * 32;
    const uint32_t b_dst = s0 + (uint32_t)(G_ASZ + (t >> 2) * G_BST + (t & 3) * 64);

#define G_LOAD(cc, stg) do { \
    const uint32_t so_ = (stg) * G_STG; \
    const __half* as_ = Asrc + (size_t)(cc) * 64; \
    const __half* bs_ = Bsrc + (size_t)(cc) * 64 * ldb; \
    _Pragma("unroll") \
    for (int i_ = 0; i_ < 4; i_++) { \
        cpa16(a_dst + so_ + i_*16, as_ + i_*8); \
        cpa16(b_dst + so_ + i_*16, bs_ + i_*8); \
    } \
} while (0)

    const int g = lane >> 3, li = lane & 7;
    const uint32_t a_frag = s0 + (uint32_t)((wm + (lane & 15)) * G_AST + (lane >> 4) * 16);
    const uint32_t b_frag = s0 + (uint32_t)(G_ASZ + ((g & 1) * 8 + li) * G_BST
                                            + (wn + (g >> 1) * 8) * 2);

    float acc[4][4][4];
#pragma unroll
    for (int i = 0; i < 4; i++)
#pragma unroll
        for (int j = 0; j < 4; j++)
#pragma unroll
            for (int k = 0; k < 4; k++) acc[i][j][k] = 0.f;

    G_LOAD(0, 0); CPA_COMMIT();
    G_LOAD(1, 1); CPA_COMMIT();

#pragma unroll 1
    for (int c = 0; c < NCH; c++) {
        CPA_WAIT(1);
        __syncthreads();
        if (c + 2 < NCH) G_LOAD(c + 2, (c + 2) % 3);
        CPA_COMMIT();

        const uint32_t so = (uint32_t)((c % 3) * G_STG);
#pragma unroll
        for (int ks = 0; ks < 4; ks++) {
            unsigned af[4][4], bf[2][4];
#pragma unroll
            for (int mt = 0; mt < 4; mt++)
                ldsm4(af[mt], a_frag + so + (uint32_t)(mt * 16 * G_AST + ks * 32));
#pragma unroll
            for (int ntp = 0; ntp < 2; ntp++)
                ldsm4t(bf[ntp], b_frag + so + (uint32_t)(ks * 16 * G_BST + ntp * 32));
#pragma unroll
            for (int mt = 0; mt < 4; mt++)
#pragma unroll
                for (int nt = 0; nt < 4; nt++)
                    mma_f16(acc[mt][nt], af[mt], bf[nt >> 1] + 2 * (nt & 1));
        }
    }

#pragma unroll
    for (int nt = 0; nt < 4; nt++) {
        const int col = n0 + wn + nt*8 + 2*lc;
        const float b0 = bias[col], b1 = bias[col + 1];
        const bool doRope = col < ropeLimit;
        const float2* rt = &g_RT[(size_t)((col & 1023) >> 1)];
#pragma unroll
        for (int mt = 0; mt < 4; mt++) {
#pragma unroll
            for (int hh = 0; hh < 2; hh++) {
                const int row = m0 + wm + mt*16 + lg + 8*hh;
                float v0 = acc[mt][nt][2*hh + 0] + b0;
                float v1 = acc[mt][nt][2*hh + 1] + b1;
                if (doRope) {
                    const float2 cs = rt[(size_t)(row & (SEQ-1)) * 512];
                    const float r0 = v0 * cs.x - v1 * cs.y;
                    v1 = v0 * cs.y + v1 * cs.x;
                    v0 = r0;
                }
                if (outHalf)
                    *(unsigned*)(Ch + (size_t)row * ldc + col) = pack_h2(v0, v1);
                else
                    *(float2*)(Cf + (size_t)row * ldc + col) = make_float2(v0, v1);
            }
        }
    }
}

// ===========================================================================
// Flash attention fp16: ldmatrix everywhere, fused QKV input,
// longest-first qt scheduling. BM=128, BN=64, 8 warps.
// ===========================================================================
#define FQSTB 144
#define FQSZB (128*FQSTB)
#define FKSZB (64*FQSTB)
#define FLASH_SMEM (FQSZB + 4*FKSZB)   // 55296

__global__ __launch_bounds__(256, 2) void flash_f16(
    const __half* __restrict__ QKV, __half* __restrict__ O)
{
    extern __shared__ char smc[];
    const uint32_t s_q = smem_u32(smc);
    const uint32_t s_k = s_q + FQSZB;
    const uint32_t s_v = s_k + 2*FKSZB;

    const int t = threadIdx.x, lane = t & 31, w = t >> 5;
    const int lg = lane >> 2, lc = lane & 3;
    const int wm = w * 16;
    const int qt = (int)(gridDim.x - 1 - blockIdx.x);   // longest-first
    const int h = blockIdx.y, b = blockIdx.z;
    const int q0 = qt * 128;

    const __half* Qb = QKV + (size_t)b * SEQ * NQKV + (size_t)h * HDIM;
    const __half* Kb = Qb + 1024;
    const __half* Vb = Qb + 2048;
    __half*       Ob = O + (size_t)b * SEQ * D_MODEL + (size_t)h * HDIM;

#define FKV_LOAD(kt_, buf) do { \
    const int r_ = t >> 2; \
    const int k0_ = (kt_) * 64; \
    const __half* kr_ = Kb + (size_t)(k0_ + r_) * NQKV; \
    const __half* vr_ = Vb + (size_t)(k0_ + r_) * NQKV; \
    _Pragma("unroll") \
    for (int i_ = 0; i_ < 2; i_++) { \
        const int gr_ = (t & 3)*2 + i_; \
        cpa16(s_k + (buf)*FKSZB + (uint32_t)(r_*FQSTB + gr_*16), kr_ + gr_*8); \
        cpa16(s_v + (buf)*FKSZB + (uint32_t)(r_*FQSTB + gr_*16), vr_ + gr_*8); \
    } \
} while (0)

    {
        const int r = t >> 1;
        const __half* qr = Qb + (size_t)(q0 + r) * NQKV;
#pragma unroll
        for (int i = 0; i < 4; i++) {
            const int gr = (t & 1)*4 + i;
            cpa16(s_q + (uint32_t)(r*FQSTB + gr*16), qr + gr*8);
        }
    }
    FKV_LOAD(0, 0);
    CPA_COMMIT();

    float accO[8][4];
#pragma unroll
    for (int i = 0; i < 8; i++)
#pragma unroll
        for (int j = 0; j < 4; j++) accO[i][j] = 0.f;
    float m0 = -1e30f, m1 = -1e30f, l0 = 0.f, l1 = 0.f;

    const float QSC = 0.125f * 1.4426950408889634f;
    const int ntiles = 2*qt + 2;

    const uint32_t q_frag = s_q + (uint32_t)((wm + (lane & 15)) * FQSTB + (lane >> 4) * 16);
    const uint32_t k_frag = (uint32_t)((lane & 15) * FQSTB + (lane >> 4) * 16);

#pragma unroll 1
    for (int kt = 0; kt < ntiles; kt++) {
        const int k0 = kt * 64;
        const int buf = kt & 1;
        CPA_WAIT(0);
        __syncthreads();
        if (kt + 1 < ntiles) FKV_LOAD(kt + 1, buf ^ 1);
        CPA_COMMIT();

        if (k0 <= q0 + wm + 15) {
            const uint32_t kb = s_k + buf*FKSZB + k_frag;

            float accS[8][4];
#pragma unroll
            for (int i = 0; i < 8; i++)
#pragma unroll
                for (int j = 0; j < 4; j++) accS[i][j] = 0.f;
#pragma unroll
            for (int ks = 0; ks < 4; ks++) {
                unsigned a[4];
                ldsm4(a, q_frag + ks*32);
#pragma unroll
                for (int ntp = 0; ntp < 4; ntp++) {
                    unsigned kq[4];
                    ldsm4(kq, kb + (uint32_t)(ntp*16*FQSTB + ks*32));
                    unsigned b0[2] = {kq[0], kq[2]};
                    unsigned b1[2] = {kq[1], kq[3]};
                    mma_f16(accS[2*ntp],     a, b0);
                    mma_f16(accS[2*ntp + 1], a, b1);
                }
            }

#pragma unroll
            for (int nt = 0; nt < 8; nt++) {
                accS[nt][0] *= QSC; accS[nt][1] *= QSC;
                accS[nt][2] *= QSC; accS[nt][3] *= QSC;
            }

            if (k0 + 63 > q0 + wm) {
                const int r0g = q0 + wm + lg, r1g = r0g + 8;
#pragma unroll
                for (int nt = 0; nt < 8; nt++) {
                    const int c = k0 + nt*8 + 2*lc;
                    if (c     > r0g) accS[nt][0] = -1e30f;
                    if (c + 1 > r0g) accS[nt][1] = -1e30f;
                    if (c     > r1g) accS[nt][2] = -1e30f;
                    if (c + 1 > r1g) accS[nt][3] = -1e30f;
                }
            }

            float mx0 = -1e30f, mx1 = -1e30f;
#pragma unroll
            for (int nt = 0; nt < 8; nt++) {
                mx0 = fmaxf(mx0, fmaxf(accS[nt][0], accS[nt][1]));
                mx1 = fmaxf(mx1, fmaxf(accS[nt][2], accS[nt][3]));
            }
            mx0 = fmaxf(mx0, __shfl_xor_sync(0xffffffffu, mx0, 1));
            mx0 = fmaxf(mx0, __shfl_xor_sync(0xffffffffu, mx0, 2));
            mx1 = fmaxf(mx1, __shfl_xor_sync(0xffffffffu, mx1, 1));
            mx1 = fmaxf(mx1, __shfl_xor_sync(0xffffffffu, mx1, 2));
            const float mn0 = fmaxf(m0, mx0), mn1 = fmaxf(m1, mx1);
            const float al0 = fexp2(m0 - mn0), al1 = fexp2(m1 - mn1);
            float s0 = 0.f, s1 = 0.f;
#pragma unroll
            for (int nt = 0; nt < 8; nt++) {
                accS[nt][0] = fexp2(accS[nt][0] - mn0);
                accS[nt][1] = fexp2(accS[nt][1] - mn0);
                accS[nt][2] = fexp2(accS[nt][2] - mn1);
                accS[nt][3] = fexp2(accS[nt][3] - mn1);
                s0 += accS[nt][0] + accS[nt][1];
                s1 += accS[nt][2] + accS[nt][3];
            }
            s0 += __shfl_xor_sync(0xffffffffu, s0, 1);
            s0 += __shfl_xor_sync(0xffffffffu, s0, 2);
            s1 += __shfl_xor_sync(0xffffffffu, s1, 1);
            s1 += __shfl_xor_sync(0xffffffffu, s1, 2);
            l0 = l0*al0 + s0;  l1 = l1*al1 + s1;
            m0 = mn0;          m1 = mn1;
#pragma unroll
            for (int nt = 0; nt < 8; nt++) {
                accO[nt][0] *= al0; accO[nt][1] *= al0;
                accO[nt][2] *= al1; accO[nt][3] *= al1;
            }

            const uint32_t vb = s_v + buf*FKSZB;
            const int g2 = lane >> 3, li = lane & 7;
#pragma unroll
            for (int ks2 = 0; ks2 < 4; ks2++) {
                unsigned aP[4];
                aP[0] = pack_h2(accS[2*ks2][0],     accS[2*ks2][1]);
                aP[1] = pack_h2(accS[2*ks2][2],     accS[2*ks2][3]);
                aP[2] = pack_h2(accS[2*ks2 + 1][0], accS[2*ks2 + 1][1]);
                aP[3] = pack_h2(accS[2*ks2 + 1][2], accS[2*ks2 + 1][3]);
#pragma unroll
                for (int ntp = 0; ntp < 4; ntp++) {
                    unsigned r[4];
                    const uint32_t addr = vb
                        + (uint32_t)((ks2*16 + (g2 & 1)*8 + li) * FQSTB
                                     + (ntp*16 + (g2 >> 1)*8) * 2);
                    ldsm4t(r, addr);
                    mma_f16(accO[2*ntp],     aP, r);
                    mma_f16(accO[2*ntp + 1], aP, r + 2);
                }
            }
        }
    }

    const float inv0 = 1.f / l0, inv1 = 1.f / l1;
    const int r0g = q0 + wm + lg, r1g = r0g + 8;
#pragma unroll
    for (int nt = 0; nt < 8; nt++) {
        const int col = nt*8 + 2*lc;
        *(unsigned*)(Ob + (size_t)r0g * D_MODEL + col) =
            pack_h2(accO[nt][0]*inv0, accO[nt][1]*inv0);
        *(unsigned*)(Ob + (size_t)r1g * D_MODEL + col) =
            pack_h2(accO[nt][2]*inv1, accO[nt][3]*inv1);
    }
}

// ===========================================================================
extern "C" void kernel_launch(void* const* d_in, const int* in_sizes, int n_in,
                              void* d_out, int out_size)
{
    const float* X  = (const float*)d_in[0];
    const float* Wq = (const float*)d_in[1];
    const float* bq = (const float*)d_in[2];
    const float* Wk = (const float*)d_in[3];
    const float* bk = (const float*)d_in[4];
    const float* Wv = (const float*)d_in[5];
    const float* bv = (const float*)d_in[6];
    const float* Wo = (const float*)d_in[7];
    const float* bo = (const float*)d_in[8];
    float* out = (float*)d_out;

    __half *x16, *wqkv, *wo16, *qkv, *ap;
    float* bqkv;
    cudaGetSymbolAddress((void**)&x16,  g_X16);
    cudaGetSymbolAddress((void**)&wqkv, g_Wqkv);
    cudaGetSymbolAddress((void**)&wo16, g_Wo16);
    cudaGetSymbolAddress((void**)&bqkv, g_Bqkv);
    cudaGetSymbolAddress((void**)&qkv,  g_QKV);
    cudaGetSymbolAddress((void**)&ap,   g_A16);

    cudaFuncSetAttribute(gemm_f16,  cudaFuncAttributeMaxDynamicSharedMemorySize, GEMM_SMEM);
    cudaFuncSetAttribute(flash_f16, cudaFuncAttributeMaxDynamicSharedMemorySize, FLASH_SMEM);

    cvtX<<<(size_t)MTOT * D_MODEL / (256*8), 256>>>((const float4*)X, x16);
    cvtW4<<<(unsigned)(4 * WCHUNK / 256), 256>>>((const float4*)Wq, (const float4*)Wk,
                                                 (const float4*)Wv, (const float4*)Wo);
    fuse_bias<<<NQKV/256, 256>>>(bq, bk, bv);
    rope_table<<<SEQ*512/256, 256>>>();

    // launch #5: fused QKV projection (N = 3072) — profiled by ncu -s 5
    gemm_f16<<<dim3(NQKV/128, MTOT/128), 256, GEMM_SMEM>>>(
        x16, wqkv, bqkv, nullptr, qkv, 1, 2048, NQKV, NQKV);

    flash_f16<<<dim3(SEQ/128, NHEADS, BATCH), 256, FLASH_SMEM>>>(qkv, ap);

    gemm_f16<<<dim3(D_MODEL/128, MTOT/128), 256, GEMM_SMEM>>>(
        ap, wo16, bo, out, nullptr, 0, 0, D_MODEL, D_MODEL);
}

// round 11
// speedup vs baseline: 1.1069x; 1.1069x over previous
#include <cuda_runtime.h>
#include <cuda_fp16.h>
#include <math.h>
#include <stdint.h>

#define D_MODEL 1024
#define SEQ     2048
#define NHEADS  16
#define HDIM    64
#define BATCH   4
#define MTOT    (BATCH*SEQ)
#define NQKV    3072

// Scratch (allocation-free rule: __device__ globals)
__device__ __half g_X16[(size_t)MTOT * D_MODEL];
__device__ __half g_Wqkv[(size_t)D_MODEL * NQKV];     // [k][3*1024] interleaved
__device__ __half g_Wo16[(size_t)D_MODEL * D_MODEL];
__device__ float  g_Bqkv[NQKV];
__device__ __half g_QKV[(size_t)MTOT * NQKV];         // fused Q|K|V rows
__device__ __half g_A16[(size_t)MTOT * D_MODEL];
__device__ float2 g_RT[(size_t)SEQ * 512];            // RoPE cos/sin table

// ---------------------------------------------------------------------------
// helpers
// ---------------------------------------------------------------------------
__device__ __forceinline__ void mma_f16(float* d, const unsigned* a, const unsigned* b) {
    asm volatile(
        "mma.sync.aligned.m16n8k16.row.col.f32.f16.f16.f32 "
        "{%0,%1,%2,%3}, {%4,%5,%6,%7}, {%8,%9}, {%0,%1,%2,%3};\n"
        : "+f"(d[0]), "+f"(d[1]), "+f"(d[2]), "+f"(d[3])
        : "r"(a[0]), "r"(a[1]), "r"(a[2]), "r"(a[3]), "r"(b[0]), "r"(b[1]));
}
__device__ __forceinline__ unsigned pack_h2(float lo, float hi) {
    unsigned r; asm("cvt.rn.f16x2.f32 %0, %1, %2;" : "=r"(r) : "f"(hi), "f"(lo));
    return r;
}
__device__ __forceinline__ void ldsm4(unsigned* r, uint32_t addr) {
    asm volatile("ldmatrix.sync.aligned.m8n8.x4.shared.b16 {%0,%1,%2,%3}, [%4];"
                 : "=r"(r[0]), "=r"(r[1]), "=r"(r[2]), "=r"(r[3]) : "r"(addr));
}
__device__ __forceinline__ void ldsm4t(unsigned* r, uint32_t addr) {
    asm volatile("ldmatrix.sync.aligned.m8n8.x4.trans.shared.b16 {%0,%1,%2,%3}, [%4];"
                 : "=r"(r[0]), "=r"(r[1]), "=r"(r[2]), "=r"(r[3]) : "r"(addr));
}
__device__ __forceinline__ uint32_t smem_u32(const void* p) {
    uint32_t a;
    asm("{ .reg .u64 t; cvta.to.shared.u64 t, %1; cvt.u32.u64 %0, t; }" : "=r"(a) : "l"(p));
    return a;
}
__device__ __forceinline__ void cpa16(uint32_t dst, const void* src) {
    asm volatile("cp.async.cg.shared.global [%0], [%1], 16;" :: "r"(dst), "l"(src));
}
#define CPA_COMMIT() asm volatile("cp.async.commit_group;" ::: "memory")
#define CPA_WAIT(n)  asm volatile("cp.async.wait_group %0;" :: "n"(n) : "memory")

// exp2 on the FMA pipe (no MUFU). Valid for x <= ~0; clamps at -125.
__device__ __forceinline__ float fexp2(float x) {
    x = fmaxf(x, -125.f);
    float t = x + 12582912.f;
    int  ix = __float_as_int(t) - 0x4B400000;
    float f = x - (t - 12582912.f);
    float p = 1.3333558146e-3f;
    p = fmaf(p, f, 9.6181291076e-3f);
    p = fmaf(p, f, 5.5504108665e-2f);
    p = fmaf(p, f, 2.4022650696e-1f);
    p = fmaf(p, f, 6.9314718056e-1f);
    p = fmaf(p, f, 1.0f);
    return p * __int_as_float((ix + 127) << 23);
}

// ===========================================================================
// converters
// ===========================================================================
__global__ __launch_bounds__(256) void cvtX(const float4* __restrict__ X4,
                                            __half* __restrict__ O) {
    const size_t i = (size_t)blockIdx.x * 256 + threadIdx.x;
    float4 a = X4[2*i], b = X4[2*i + 1];
    uint4 o;
    o.x = pack_h2(a.x, a.y); o.y = pack_h2(a.z, a.w);
    o.z = pack_h2(b.x, b.y); o.w = pack_h2(b.z, b.w);
    *(uint4*)(O + 8*i) = o;
}
// All four weight matrices in one launch. Wq/Wk/Wv -> interleaved [k][3072];
// Wo -> flat fp16.
#define WCHUNK ((size_t)D_MODEL * D_MODEL / 8)
__global__ __launch_bounds__(256) void cvtW4(
    const float4* __restrict__ Wq, const float4* __restrict__ Wk,
    const float4* __restrict__ Wv, const float4* __restrict__ Wo) {
    const size_t gi = (size_t)blockIdx.x * 256 + threadIdx.x;
    const int which = (int)(gi / WCHUNK);
    const size_t j = gi % WCHUNK;
    const float4* src = (which == 0) ? Wq : (which == 1) ? Wk : (which == 2) ? Wv : Wo;
    float4 a = src[2*j], b = src[2*j + 1];
    uint4 o;
    o.x = pack_h2(a.x, a.y); o.y = pack_h2(a.z, a.w);
    o.z = pack_h2(b.x, b.y); o.w = pack_h2(b.z, b.w);
    if (which < 3) {
        const size_t k = (8*j) >> 10, n = (8*j) & 1023;
        *(uint4*)(g_Wqkv + k * NQKV + which * 1024 + n) = o;
    } else {
        *(uint4*)(g_Wo16 + 8*j) = o;
    }
}
__global__ __launch_bounds__(256) void fuse_bias(const float* __restrict__ bq,
                                                 const float* __restrict__ bk,
                                                 const float* __restrict__ bv) {
    const int i = blockIdx.x * 256 + threadIdx.x;
    g_Bqkv[i] = (i < 1024) ? bq[i] : (i < 2048 ? bk[i - 1024] : bv[i - 2048]);
}
__global__ __launch_bounds__(256) void rope_table() {
    const int i = blockIdx.x * 256 + threadIdx.x;
    const int pos = i >> 9, p = i & 511;
    const float NEG_L2B = -0.02595256324130752f;
    const float fr = exp2f((float)p * NEG_L2B);
    float s, c; sincosf((float)pos * fr, &s, &c);
    g_RT[i] = make_float2(c, s);
}

// ===========================================================================
// fp16 GEMM (m16n8k16): C = A16 @ W16 + bias, RoPE iff col < ropeLimit.
// CTA 128x128, BK=32, 4-stage cp.async, ldmatrix fragments.
// ===========================================================================
#define G_AST 80
#define G_BST 272
#define G_ASZ (128*G_AST)            // 10240
#define G_BSZ (32*G_BST)             // 8704
#define G_STG (G_ASZ + G_BSZ)        // 18944
#define GEMM_SMEM (4*G_STG)          // 75776 B
#define NCH (D_MODEL/32)             // 32

__global__ __launch_bounds__(256, 2) void gemm_f16(
    const __half* __restrict__ A16, const __half* __restrict__ W16,
    const float* __restrict__ bias, float* __restrict__ Cf,
    __half* __restrict__ Ch, int outHalf, int ropeLimit, int ldb, int ldc)
{
    extern __shared__ char smc[];
    const uint32_t s0 = smem_u32(smc);

    const int t = threadIdx.x, lane = t & 31, wid = t >> 5;
    const int lg = lane >> 2, lc = lane & 3;
    const int wm = (wid >> 2) * 64, wn = (wid & 3) * 32;
    const int m0 = blockIdx.y * 128, n0 = blockIdx.x * 128;

    const __half* Asrc = A16 + (size_t)(m0 + (t >> 1)) * D_MODEL + (t & 1) * 16;
    const uint32_t a_dst = s0 + (uint32_t)((t >> 1) * G_AST + (t & 1) * 32);
    const int b_kr = t >> 3, b_sg = t & 7;
    const __half* Bsrc = W16 + (size_t)b_kr * ldb + n0 + b_sg * 8;
    const uint32_t b_dst = s0 + (uint32_t)(G_ASZ + b_kr * G_BST + b_sg * 16);

#define G_LOAD(cc, stg) do { \
    const uint32_t so_ = (stg) * G_STG; \
    const __half* as_ = Asrc + (size_t)(cc) * 32; \
    cpa16(a_dst + so_,      as_); \
    cpa16(a_dst + so_ + 16, as_ + 8); \
    const __half* bs_ = Bsrc + (size_t)(cc) * 32 * ldb; \
    cpa16(b_dst + so_,       bs_); \
    cpa16(b_dst + so_ + 128, bs_ + 64); \
} while (0)

    const int g = lane >> 3, li = lane & 7;
    const uint32_t a_frag = s0 + (uint32_t)((wm + (lane & 15)) * G_AST + (lane >> 4) * 16);
    const uint32_t b_frag = s0 + (uint32_t)(G_ASZ + ((g & 1) * 8 + li) * G_BST
                                            + (wn + (g >> 1) * 8) * 2);

    float acc[4][4][4];
#pragma unroll
    for (int i = 0; i < 4; i++)
#pragma unroll
        for (int j = 0; j < 4; j++)
#pragma unroll
            for (int k = 0; k < 4; k++) acc[i][j][k] = 0.f;

    G_LOAD(0, 0); CPA_COMMIT();
    G_LOAD(1, 1); CPA_COMMIT();
    G_LOAD(2, 2); CPA_COMMIT();

#pragma unroll 1
    for (int c = 0; c < NCH; c++) {
        CPA_WAIT(2);
        __syncthreads();
        if (c + 3 < NCH) G_LOAD(c + 3, (c + 3) & 3);
        CPA_COMMIT();

        const uint32_t so = (uint32_t)((c & 3) * G_STG);
#pragma unroll
        for (int ks = 0; ks < 2; ks++) {
            unsigned af[4][4], bf[2][4];
#pragma unroll
            for (int mt = 0; mt < 4; mt++)
                ldsm4(af[mt], a_frag + so + (uint32_t)(mt * 16 * G_AST + ks * 32));
#pragma unroll
            for (int ntp = 0; ntp < 2; ntp++)
                ldsm4t(bf[ntp], b_frag + so + (uint32_t)(ks * 16 * G_BST + ntp * 32));
#pragma unroll
            for (int mt = 0; mt < 4; mt++)
#pragma unroll
                for (int nt = 0; nt < 4; nt++)
                    mma_f16(acc[mt][nt], af[mt], bf[nt >> 1] + 2 * (nt & 1));
        }
    }

#pragma unroll
    for (int nt = 0; nt < 4; nt++) {
        const int col = n0 + wn + nt*8 + 2*lc;
        const float b0 = bias[col], b1 = bias[col + 1];
        const bool doRope = col < ropeLimit;
        const float2* rt = &g_RT[(size_t)((col & 1023) >> 1)];
#pragma unroll
        for (int mt = 0; mt < 4; mt++) {
#pragma unroll
            for (int hh = 0; hh < 2; hh++) {
                const int row = m0 + wm + mt*16 + lg + 8*hh;
                float v0 = acc[mt][nt][2*hh + 0] + b0;
                float v1 = acc[mt][nt][2*hh + 1] + b1;
                if (doRope) {
                    const float2 cs = rt[(size_t)(row & (SEQ-1)) * 512];
                    const float r0 = v0 * cs.x - v1 * cs.y;
                    v1 = v0 * cs.y + v1 * cs.x;
                    v0 = r0;
                }
                if (outHalf)
                    *(unsigned*)(Ch + (size_t)row * ldc + col) = pack_h2(v0, v1);
                else
                    *(float2*)(Cf + (size_t)row * ldc + col) = make_float2(v0, v1);
            }
        }
    }
}

// ===========================================================================
// Flash attention fp16 (R9 exact): ldmatrix everywhere, fused QKV input.
// BM=128, BN=64, 8 warps.
// ===========================================================================
#define FQSTB 144
#define FQSZB (128*FQSTB)
#define FKSZB (64*FQSTB)
#define FLASH_SMEM (FQSZB + 4*FKSZB)   // 55296

__global__ __launch_bounds__(256, 2) void flash_f16(
    const __half* __restrict__ QKV, __half* __restrict__ O)
{
    extern __shared__ char smc[];
    const uint32_t s_q = smem_u32(smc);
    const uint32_t s_k = s_q + FQSZB;
    const uint32_t s_v = s_k + 2*FKSZB;

    const int t = threadIdx.x, lane = t & 31, w = t >> 5;
    const int lg = lane >> 2, lc = lane & 3;
    const int wm = w * 16;
    const int qt = blockIdx.x, h = blockIdx.y, b = blockIdx.z;
    const int q0 = qt * 128;

    const __half* Qb = QKV + (size_t)b * SEQ * NQKV + (size_t)h * HDIM;
    const __half* Kb = Qb + 1024;
    const __half* Vb = Qb + 2048;
    __half*       Ob = O + (size_t)b * SEQ * D_MODEL + (size_t)h * HDIM;

#define FKV_LOAD(kt_, buf) do { \
    const int r_ = t >> 2; \
    const int k0_ = (kt_) * 64; \
    const __half* kr_ = Kb + (size_t)(k0_ + r_) * NQKV; \
    const __half* vr_ = Vb + (size_t)(k0_ + r_) * NQKV; \
    _Pragma("unroll") \
    for (int i_ = 0; i_ < 2; i_++) { \
        const int gr_ = (t & 3)*2 + i_; \
        cpa16(s_k + (buf)*FKSZB + (uint32_t)(r_*FQSTB + gr_*16), kr_ + gr_*8); \
        cpa16(s_v + (buf)*FKSZB + (uint32_t)(r_*FQSTB + gr_*16), vr_ + gr_*8); \
    } \
} while (0)

    {
        const int r = t >> 1;
        const __half* qr = Qb + (size_t)(q0 + r) * NQKV;
#pragma unroll
        for (int i = 0; i < 4; i++) {
            const int gr = (t & 1)*4 + i;
            cpa16(s_q + (uint32_t)(r*FQSTB + gr*16), qr + gr*8);
        }
    }
    FKV_LOAD(0, 0);
    CPA_COMMIT();

    float accO[8][4];
#pragma unroll
    for (int i = 0; i < 8; i++)
#pragma unroll
        for (int j = 0; j < 4; j++) accO[i][j] = 0.f;
    float m0 = -1e30f, m1 = -1e30f, l0 = 0.f, l1 = 0.f;

    const float QSC = 0.125f * 1.4426950408889634f;
    const int ntiles = 2*qt + 2;

    const uint32_t q_frag = s_q + (uint32_t)((wm + (lane & 15)) * FQSTB + (lane >> 4) * 16);
    const uint32_t k_frag = (uint32_t)((lane & 15) * FQSTB + (lane >> 4) * 16);

#pragma unroll 1
    for (int kt = 0; kt < ntiles; kt++) {
        const int k0 = kt * 64;
        const int buf = kt & 1;
        CPA_WAIT(0);
        __syncthreads();
        if (kt + 1 < ntiles) FKV_LOAD(kt + 1, buf ^ 1);
        CPA_COMMIT();

        if (k0 <= q0 + wm + 15) {
            const uint32_t kb = s_k + buf*FKSZB + k_frag;

            float accS[8][4];
#pragma unroll
            for (int i = 0; i < 8; i++)
#pragma unroll
                for (int j = 0; j < 4; j++) accS[i][j] = 0.f;
#pragma unroll
            for (int ks = 0; ks < 4; ks++) {
                unsigned a[4];
                ldsm4(a, q_frag + ks*32);
#pragma unroll
                for (int ntp = 0; ntp < 4; ntp++) {
                    unsigned kq[4];
                    ldsm4(kq, kb + (uint32_t)(ntp*16*FQSTB + ks*32));
                    unsigned b0[2] = {kq[0], kq[2]};
                    unsigned b1[2] = {kq[1], kq[3]};
                    mma_f16(accS[2*ntp],     a, b0);
                    mma_f16(accS[2*ntp + 1], a, b1);
                }
            }

#pragma unroll
            for (int nt = 0; nt < 8; nt++) {
                accS[nt][0] *= QSC; accS[nt][1] *= QSC;
                accS[nt][2] *= QSC; accS[nt][3] *= QSC;
            }

            if (k0 + 63 > q0 + wm) {
                const int r0g = q0 + wm + lg, r1g = r0g + 8;
#pragma unroll
                for (int nt = 0; nt < 8; nt++) {
                    const int c = k0 + nt*8 + 2*lc;
                    if (c     > r0g) accS[nt][0] = -1e30f;
                    if (c + 1 > r0g) accS[nt][1] = -1e30f;
                    if (c     > r1g) accS[nt][2] = -1e30f;
                    if (c + 1 > r1g) accS[nt][3] = -1e30f;
                }
            }

            float mx0 = -1e30f, mx1 = -1e30f;
#pragma unroll
            for (int nt = 0; nt < 8; nt++) {
                mx0 = fmaxf(mx0, fmaxf(accS[nt][0], accS[nt][1]));
                mx1 = fmaxf(mx1, fmaxf(accS[nt][2], accS[nt][3]));
            }
            mx0 = fmaxf(mx0, __shfl_xor_sync(0xffffffffu, mx0, 1));
            mx0 = fmaxf(mx0, __shfl_xor_sync(0xffffffffu, mx0, 2));
            mx1 = fmaxf(mx1, __shfl_xor_sync(0xffffffffu, mx1, 1));
            mx1 = fmaxf(mx1, __shfl_xor_sync(0xffffffffu, mx1, 2));
            const float mn0 = fmaxf(m0, mx0), mn1 = fmaxf(m1, mx1);
            const float al0 = fexp2(m0 - mn0), al1 = fexp2(m1 - mn1);
            float s0 = 0.f, s1 = 0.f;
#pragma unroll
            for (int nt = 0; nt < 8; nt++) {
                accS[nt][0] = fexp2(accS[nt][0] - mn0);
                accS[nt][1] = fexp2(accS[nt][1] - mn0);
                accS[nt][2] = fexp2(accS[nt][2] - mn1);
                accS[nt][3] = fexp2(accS[nt][3] - mn1);
                s0 += accS[nt][0] + accS[nt][1];
                s1 += accS[nt][2] + accS[nt][3];
            }
            s0 += __shfl_xor_sync(0xffffffffu, s0, 1);
            s0 += __shfl_xor_sync(0xffffffffu, s0, 2);
            s1 += __shfl_xor_sync(0xffffffffu, s1, 1);
            s1 += __shfl_xor_sync(0xffffffffu, s1, 2);
            l0 = l0*al0 + s0;  l1 = l1*al1 + s1;
            m0 = mn0;          m1 = mn1;
#pragma unroll
            for (int nt = 0; nt < 8; nt++) {
                accO[nt][0] *= al0; accO[nt][1] *= al0;
                accO[nt][2] *= al1; accO[nt][3] *= al1;
            }

            const uint32_t vb = s_v + buf*FKSZB;
            const int g2 = lane >> 3, li = lane & 7;
#pragma unroll
            for (int ks2 = 0; ks2 < 4; ks2++) {
                unsigned aP[4];
                aP[0] = pack_h2(accS[2*ks2][0],     accS[2*ks2][1]);
                aP[1] = pack_h2(accS[2*ks2][2],     accS[2*ks2][3]);
                aP[2] = pack_h2(accS[2*ks2 + 1][0], accS[2*ks2 + 1][1]);
                aP[3] = pack_h2(accS[2*ks2 + 1][2], accS[2*ks2 + 1][3]);
#pragma unroll
                for (int ntp = 0; ntp < 4; ntp++) {
                    unsigned r[4];
                    const uint32_t addr = vb
                        + (uint32_t)((ks2*16 + (g2 & 1)*8 + li) * FQSTB
                                     + (ntp*16 + (g2 >> 1)*8) * 2);
                    ldsm4t(r, addr);
                    mma_f16(accO[2*ntp],     aP, r);
                    mma_f16(accO[2*ntp + 1], aP, r + 2);
                }
            }
        }
    }

    const float inv0 = 1.f / l0, inv1 = 1.f / l1;
    const int r0g = q0 + wm + lg, r1g = r0g + 8;
#pragma unroll
    for (int nt = 0; nt < 8; nt++) {
        const int col = nt*8 + 2*lc;
        *(unsigned*)(Ob + (size_t)r0g * D_MODEL + col) =
            pack_h2(accO[nt][0]*inv0, accO[nt][1]*inv0);
        *(unsigned*)(Ob + (size_t)r1g * D_MODEL + col) =
            pack_h2(accO[nt][2]*inv1, accO[nt][3]*inv1);
    }
}

// ===========================================================================
extern "C" void kernel_launch(void* const* d_in, const int* in_sizes, int n_in,
                              void* d_out, int out_size)
{
    const float* X  = (const float*)d_in[0];
    const float* Wq = (const float*)d_in[1];
    const float* bq = (const float*)d_in[2];
    const float* Wk = (const float*)d_in[3];
    const float* bk = (const float*)d_in[4];
    const float* Wv = (const float*)d_in[5];
    const float* bv = (const float*)d_in[6];
    const float* Wo = (const float*)d_in[7];
    const float* bo = (const float*)d_in[8];
    float* out = (float*)d_out;

    __half *x16, *wqkv, *wo16, *qkv, *ap;
    float* bqkv;
    cudaGetSymbolAddress((void**)&x16,  g_X16);
    cudaGetSymbolAddress((void**)&wqkv, g_Wqkv);
    cudaGetSymbolAddress((void**)&wo16, g_Wo16);
    cudaGetSymbolAddress((void**)&bqkv, g_Bqkv);
    cudaGetSymbolAddress((void**)&qkv,  g_QKV);
    cudaGetSymbolAddress((void**)&ap,   g_A16);

    cudaFuncSetAttribute(gemm_f16,  cudaFuncAttributeMaxDynamicSharedMemorySize, GEMM_SMEM);
    cudaFuncSetAttribute(flash_f16, cudaFuncAttributeMaxDynamicSharedMemorySize, FLASH_SMEM);

    cvtX<<<(size_t)MTOT * D_MODEL / (256*8), 256>>>((const float4*)X, x16);
    cvtW4<<<(unsigned)(4 * WCHUNK / 256), 256>>>((const float4*)Wq, (const float4*)Wk,
                                                 (const float4*)Wv, (const float4*)Wo);
    fuse_bias<<<NQKV/256, 256>>>(bq, bk, bv);
    rope_table<<<SEQ*512/256, 256>>>();

    // fused QKV projection: N = 3072
    gemm_f16<<<dim3(NQKV/128, MTOT/128), 256, GEMM_SMEM>>>(
        x16, wqkv, bqkv, nullptr, qkv, 1, 2048, NQKV, NQKV);

    flash_f16<<<dim3(SEQ/128, NHEADS, BATCH), 256, FLASH_SMEM>>>(qkv, ap);

    // output projection: N = 1024, fp32 out
    gemm_f16<<<dim3(D_MODEL/128, MTOT/128), 256, GEMM_SMEM>>>(
        ap, wo16, bo, out, nullptr, 0, 0, D_MODEL, D_MODEL);
}